// round 15
// baseline (speedup 1.0000x reference)
#include <cuda_runtime.h>
#include <cuda_fp16.h>
#include <cstdint>

// LinearAttention B=4, N=4096, D=1024 fp32
// R15: proj = R14 (256thr, 2 CTA/SM, CTA 128x64 dual). kv/out singles now
//      512 threads x 2 CTA/SM (32 warps/SM), CTA 128x128, warp 32x32 (acc=32).

#define Bv 4
#define Nv 4096
#define Dv 1024
#define BNROWS (Bv*Nv)            // 16384

#define NST 4
#define STG 16384                 // 16KB stage (both families)
#define SMEMB (NST*STG)           // 65536

#define SWZ64(x) ((x) ^ (((x) >> 3) & 0x30))

// ------------------------------ scratch -----------------------------------
__device__ __align__(16) __half g_X  [(size_t)BNROWS*Dv];
__device__ __align__(16) __half g_WT [4][1024*1024];
__device__ __align__(16) __half g_Q  [(size_t)BNROWS*Dv];
__device__ __align__(16) __half g_KT [(size_t)Bv*Dv*Nv];
__device__ __align__(16) __half g_VT [(size_t)Bv*Dv*Nv];
__device__ __align__(16) __half g_KVT[(size_t)Bv*Dv*Dv];

// ------------------------------ helpers ------------------------------------
__device__ __forceinline__ uint32_t s2u(const void* p) {
    uint32_t a;
    asm("{ .reg .u64 t; cvta.to.shared.u64 t, %1; cvt.u32.u64 %0, t; }" : "=r"(a) : "l"(p));
    return a;
}
__device__ __forceinline__ void cpa16(uint32_t dst, const void* src) {
    asm volatile("cp.async.cg.shared.global [%0], [%1], 16;" :: "r"(dst), "l"(src));
}
#define CPC() asm volatile("cp.async.commit_group;" ::: "memory")
#define WAITG(n) asm volatile("cp.async.wait_group %0;" :: "n"(n) : "memory")

__device__ __forceinline__ void ldsm4(uint32_t* r, uint32_t addr) {
    asm volatile("ldmatrix.sync.aligned.m8n8.x4.shared.b16 {%0,%1,%2,%3}, [%4];"
                 : "=r"(r[0]), "=r"(r[1]), "=r"(r[2]), "=r"(r[3]) : "r"(addr));
}
__device__ __forceinline__ void mmaf16(float* c, const uint32_t* a, const uint32_t* b) {
    asm volatile(
        "mma.sync.aligned.m16n8k16.row.col.f32.f16.f16.f32 "
        "{%0,%1,%2,%3}, {%4,%5,%6,%7}, {%8,%9}, {%0,%1,%2,%3};"
        : "+f"(c[0]), "+f"(c[1]), "+f"(c[2]), "+f"(c[3])
        : "r"(a[0]), "r"(a[1]), "r"(a[2]), "r"(a[3]), "r"(b[0]), "r"(b[1]));
}
__device__ __forceinline__ uint32_t packh2(float f0, float f1) {
    return ((uint32_t)__half_as_ushort(__float2half_rn(f1)) << 16)
         | __half_as_ushort(__float2half_rn(f0));
}

// --------------- merged projection GEMM (dual-B, CTA 128x64) ----------------
// 256 thr, 2 CTA/SM. z=0: q=C1*C2 straight fp16. z=1: C1,C2 -> transposed.
__global__ __launch_bounds__(256, 2)
void gemm1_proj(const __half* __restrict__ Ag,
                const __half* __restrict__ W0, const __half* __restrict__ W1,
                const __half* __restrict__ W2, const __half* __restrict__ W3,
                __half* __restrict__ Q, __half* __restrict__ KT,
                __half* __restrict__ VT, int N, int Kg)
{
    extern __shared__ char sm[];
    const uint32_t smu = s2u(sm);
    const int tid = threadIdx.x, lane = tid & 31, wid = tid >> 5;
    const int bm = blockIdx.y * 128, bn = blockIdx.x * 64;
    const int wm = (wid & 3) * 32, wn = (wid >> 2) * 32;
    const int job = blockIdx.z;

    const __half* B1 = (job == 0) ? W0 : W2;
    const __half* B2 = (job == 0) ? W1 : W3;

    const int rr = tid >> 2, cg = tid & 3;                 // rr 0..63
    const uint32_t so0 = SWZ64((uint32_t)(rr * 64 + cg * 16));
    const uint32_t so1 = SWZ64((uint32_t)((rr + 64) * 64 + cg * 16));
    const __half* gA = Ag + (size_t)(bm + rr) * Kg + cg * 8;
    const __half* g1 = B1 + (size_t)(bn + rr) * Kg + cg * 8;
    const __half* g2 = B2 + (size_t)(bn + rr) * Kg + cg * 8;
    const size_t rstep = (size_t)64 * Kg;

    uint32_t aoff[2][2], boff[2][2];
    {
        uint32_t arow = (uint32_t)(wm + (lane & 15));
        uint32_t acol = (uint32_t)((lane >> 4) * 16);
        uint32_t brow = (uint32_t)(wn + ((lane >> 4) << 3) + (lane & 7));
        uint32_t bcol = (uint32_t)(((lane >> 3) & 1) * 16);
#pragma unroll
        for (int ks = 0; ks < 2; ks++) {
#pragma unroll
            for (int mi = 0; mi < 2; mi++)
                aoff[ks][mi] = SWZ64((arow + mi * 16) * 64 + ks * 32 + acol);
#pragma unroll
            for (int g = 0; g < 2; g++)
                boff[ks][g] = SWZ64((brow + g * 16) * 64 + ks * 32 + bcol);
        }
    }

    float a1[2][4][4], a2[2][4][4];
#pragma unroll
    for (int mi = 0; mi < 2; mi++)
#pragma unroll
        for (int ni = 0; ni < 4; ni++)
#pragma unroll
            for (int j = 0; j < 4; j++) { a1[mi][ni][j] = 0.0f; a2[mi][ni][j] = 0.0f; }

    const int nch = Kg / 32;
    auto load_stage = [&](int c) {
        const uint32_t st = smu + (uint32_t)(c & (NST - 1)) * STG;
        const int k0 = c * 32;
        cpa16(st + so0,           gA + k0);
        cpa16(st + so1,           gA + k0 + rstep);
        cpa16(st + 8192 + so0,    g1 + k0);
        cpa16(st + 12288 + so0,   g2 + k0);
        CPC();
    };

    load_stage(0); load_stage(1); load_stage(2);

    for (int c = 0; c < nch; ++c) {
        if (c + 3 <= nch)      WAITG(2);
        else if (c + 2 == nch) WAITG(1);
        else                   WAITG(0);
        __syncthreads();
        if (c + 3 < nch) load_stage(c + 3);

        const uint32_t st = smu + (uint32_t)(c & (NST - 1)) * STG;
#pragma unroll
        for (int ks = 0; ks < 2; ks++) {
            uint32_t ah[2][4], t1[2][4], t2[2][4];
#pragma unroll
            for (int mi = 0; mi < 2; mi++)
                ldsm4(ah[mi], st + aoff[ks][mi]);
#pragma unroll
            for (int g = 0; g < 2; g++) {
                ldsm4(t1[g], st + 8192 + boff[ks][g]);
                ldsm4(t2[g], st + 12288 + boff[ks][g]);
            }
#pragma unroll
            for (int g = 0; g < 2; g++)
#pragma unroll
                for (int mi = 0; mi < 2; mi++) {
                    mmaf16(a1[mi][2*g],   ah[mi], t1[g]);
                    mmaf16(a1[mi][2*g+1], ah[mi], t1[g] + 2);
                    mmaf16(a2[mi][2*g],   ah[mi], t2[g]);
                    mmaf16(a2[mi][2*g+1], ah[mi], t2[g] + 2);
                }
        }
    }

    if (job == 0) {
#pragma unroll
        for (int mi = 0; mi < 2; mi++) {
            int r = bm + wm + mi * 16 + (lane >> 2);
#pragma unroll
            for (int ni = 0; ni < 4; ni++) {
                int c = bn + wn + ni * 8 + (lane & 3) * 2;
                *(uint32_t*)(Q + (size_t)r * N + c) =
                    packh2(a1[mi][ni][0]*a2[mi][ni][0], a1[mi][ni][1]*a2[mi][ni][1]);
                *(uint32_t*)(Q + (size_t)(r + 8) * N + c) =
                    packh2(a1[mi][ni][2]*a2[mi][ni][2], a1[mi][ni][3]*a2[mi][ni][3]);
            }
        }
    } else {
        size_t batch = (size_t)(bm >> 12);
        size_t base = batch * (size_t)Dv * Nv + (size_t)bn * Nv + (bm & 4095);
        __half* s16 = (__half*)sm;
        const int LDS = 72;
        const float (*accs[2])[4][4] = { a1, a2 };
        __half* outs[2] = { KT, VT };
#pragma unroll
        for (int w = 0; w < 2; w++) {
            __syncthreads();
#pragma unroll
            for (int mi = 0; mi < 2; mi++) {
                int r = wm + mi * 16 + (lane >> 2);
#pragma unroll
                for (int ni = 0; ni < 4; ni++) {
                    int c = wn + ni * 8 + (lane & 3) * 2;
                    s16[r * LDS + c]           = __float2half_rn(accs[w][mi][ni][0]);
                    s16[r * LDS + c + 1]       = __float2half_rn(accs[w][mi][ni][1]);
                    s16[(r + 8) * LDS + c]     = __float2half_rn(accs[w][mi][ni][2]);
                    s16[(r + 8) * LDS + c + 1] = __float2half_rn(accs[w][mi][ni][3]);
                }
            }
            __syncthreads();
            int d = tid >> 2, nb = (tid & 3) * 32;
            __half* rh = outs[w] + base + (size_t)d * Nv + nb;
#pragma unroll
            for (int j = 0; j < 4; j++) {
                alignas(16) __half hb[8];
#pragma unroll
                for (int i = 0; i < 8; i++)
                    hb[i] = s16[(nb + j * 8 + i) * LDS + d];
                *(uint4*)(rh + j * 8) = *(const uint4*)hb;
            }
        }
    }
}

// --------------- single-B 1-pass GEMM (kv / out), 512 thr, 2 CTA/SM ---------
// CTA 128x128, 16 warps, warp 32x32 (acc=32 regs). MODE 0: fp32. MODE 1: trans fp16.
template<int MODE>
__global__ __launch_bounds__(512, 2)
void gemm1(const __half* __restrict__ Ag, const __half* __restrict__ Bg,
           float* __restrict__ Cf, __half* __restrict__ OH,
           int M, int N, int Kg, long sA, long sB, long sO)
{
    extern __shared__ char sm[];
    const uint32_t smu = s2u(sm);
    const int tid = threadIdx.x, lane = tid & 31, wid = tid >> 5;
    const int bm = blockIdx.y * 128, bn = blockIdx.x * 128;
    const int wm = (wid & 3) * 32, wn = (wid >> 2) * 32;

    const __half* Ap = Ag + (size_t)blockIdx.z * sA;
    const __half* Bp = Bg + (size_t)blockIdx.z * sB;

    const int rr = tid >> 2, cg = tid & 3;                 // rr 0..127
    const uint32_t so = SWZ64((uint32_t)(rr * 64 + cg * 16));
    const __half* gA = Ap + (size_t)(bm + rr) * Kg + cg * 8;
    const __half* gB = Bp + (size_t)(bn + rr) * Kg + cg * 8;

    uint32_t aoff[2][2], boff[2][2];
    {
        uint32_t arow = (uint32_t)(wm + (lane & 15));
        uint32_t acol = (uint32_t)((lane >> 4) * 16);
        uint32_t brow = (uint32_t)(wn + ((lane >> 4) << 3) + (lane & 7));
        uint32_t bcol = (uint32_t)(((lane >> 3) & 1) * 16);
#pragma unroll
        for (int ks = 0; ks < 2; ks++) {
#pragma unroll
            for (int mi = 0; mi < 2; mi++)
                aoff[ks][mi] = SWZ64((arow + mi * 16) * 64 + ks * 32 + acol);
#pragma unroll
            for (int g = 0; g < 2; g++)
                boff[ks][g] = SWZ64((brow + g * 16) * 64 + ks * 32 + bcol);
        }
    }

    float acc[2][4][4];
#pragma unroll
    for (int mi = 0; mi < 2; mi++)
#pragma unroll
        for (int ni = 0; ni < 4; ni++)
#pragma unroll
            for (int j = 0; j < 4; j++) acc[mi][ni][j] = 0.0f;

    const int nch = Kg / 32;
    auto load_stage = [&](int c) {
        const uint32_t st = smu + (uint32_t)(c & (NST - 1)) * STG;
        const int k0 = c * 32;
        cpa16(st + so,         gA + k0);
        cpa16(st + 8192 + so,  gB + k0);
        CPC();
    };

    load_stage(0); load_stage(1); load_stage(2);

    for (int c = 0; c < nch; ++c) {
        if (c + 3 <= nch)      WAITG(2);
        else if (c + 2 == nch) WAITG(1);
        else                   WAITG(0);
        __syncthreads();
        if (c + 3 < nch) load_stage(c + 3);

        const uint32_t st = smu + (uint32_t)(c & (NST - 1)) * STG;
#pragma unroll
        for (int ks = 0; ks < 2; ks++) {
            uint32_t ah[2][4], tb[2][4];
#pragma unroll
            for (int mi = 0; mi < 2; mi++)
                ldsm4(ah[mi], st + aoff[ks][mi]);
#pragma unroll
            for (int g = 0; g < 2; g++)
                ldsm4(tb[g], st + 8192 + boff[ks][g]);
#pragma unroll
            for (int g = 0; g < 2; g++)
#pragma unroll
                for (int mi = 0; mi < 2; mi++) {
                    mmaf16(acc[mi][2*g],   ah[mi], tb[g]);
                    mmaf16(acc[mi][2*g+1], ah[mi], tb[g] + 2);
                }
        }
    }

    if (MODE == 0) {
        float* Cb = Cf + (size_t)blockIdx.z * sO;
#pragma unroll
        for (int mi = 0; mi < 2; mi++) {
            int rA = bm + wm + mi * 16 + (lane >> 2);
#pragma unroll
            for (int ni = 0; ni < 4; ni++) {
                int col = bn + wn + ni * 8 + (lane & 3) * 2;
                *(float2*)(Cb + (size_t)rA * N + col)       = make_float2(acc[mi][ni][0], acc[mi][ni][1]);
                *(float2*)(Cb + (size_t)(rA + 8) * N + col) = make_float2(acc[mi][ni][2], acc[mi][ni][3]);
            }
        }
    } else {
        // transpose 128x128 tile -> fp16 rows (bn+d), cols bm.. (LDS=136 halfs)
        size_t base = (size_t)blockIdx.z * sO + (size_t)bn * M + bm;
        __half* s16 = (__half*)sm;
        const int LDS = 136;
        __syncthreads();
#pragma unroll
        for (int mi = 0; mi < 2; mi++) {
            int r = wm + mi * 16 + (lane >> 2);
#pragma unroll
            for (int ni = 0; ni < 4; ni++) {
                int c = wn + ni * 8 + (lane & 3) * 2;
                s16[r * LDS + c]           = __float2half_rn(acc[mi][ni][0]);
                s16[r * LDS + c + 1]       = __float2half_rn(acc[mi][ni][1]);
                s16[(r + 8) * LDS + c]     = __float2half_rn(acc[mi][ni][2]);
                s16[(r + 8) * LDS + c + 1] = __float2half_rn(acc[mi][ni][3]);
            }
        }
        __syncthreads();
        int d = tid >> 2, nb = (tid & 3) * 32;              // d 0..127, 32 cols each
        __half* rh = OH + base + (size_t)d * M + nb;
#pragma unroll
        for (int j = 0; j < 4; j++) {
            alignas(16) __half hb[8];
#pragma unroll
            for (int i = 0; i < 8; i++)
                hb[i] = s16[(nb + j * 8 + i) * LDS + d];
            *(uint4*)(rh + j * 8) = *(const uint4*)hb;
        }
    }
}

// --------------------------- conversion kernels ----------------------------
__global__ void conv_x(const float* __restrict__ in, __half* __restrict__ o) {
    size_t i = (size_t)blockIdx.x * blockDim.x + threadIdx.x;
    float4 f = ((const float4*)in)[i];
    ((__half2*)o)[i*2]   = __halves2half2(__float2half_rn(f.x), __float2half_rn(f.y));
    ((__half2*)o)[i*2+1] = __halves2half2(__float2half_rn(f.z), __float2half_rn(f.w));
}

__global__ void conv_wT(const float* w0, const float* w1, const float* w2, const float* w3,
                        __half* __restrict__ O) {
    const float* in = (blockIdx.z == 0) ? w0 : (blockIdx.z == 1) ? w1
                     : (blockIdx.z == 2) ? w2 : w3;
    __half* o = O + (size_t)blockIdx.z * Dv * Dv;
    __shared__ float t[32][33];
    int c0 = blockIdx.x * 32, r0 = blockIdx.y * 32;
    int tx = threadIdx.x, ty = threadIdx.y;
#pragma unroll
    for (int i = 0; i < 4; i++)
        t[ty + i*8][tx] = in[(size_t)(r0 + ty + i*8) * Dv + c0 + tx];
    __syncthreads();
#pragma unroll
    for (int i = 0; i < 4; i++) {
        int oc = c0 + ty + i*8, od = r0 + tx;
        o[(size_t)oc * Dv + od] = __float2half_rn(t[tx][ty + i*8]);
    }
}

// ------------------------------- launch ------------------------------------
extern "C" void kernel_launch(void* const* d_in, const int* in_sizes, int n_in,
                              void* d_out, int out_size) {
    const float* x   = (const float*)d_in[0];
    const float* w[4] = { (const float*)d_in[1], (const float*)d_in[2],
                          (const float*)d_in[3], (const float*)d_in[4] };
    float* out = (float*)d_out;

    __half *X,*WT,*Q,*KT,*VT,*KVT;
    cudaGetSymbolAddress((void**)&X,   g_X);
    cudaGetSymbolAddress((void**)&WT,  g_WT);
    cudaGetSymbolAddress((void**)&Q,   g_Q);
    cudaGetSymbolAddress((void**)&KT,  g_KT);  cudaGetSymbolAddress((void**)&VT,  g_VT);
    cudaGetSymbolAddress((void**)&KVT, g_KVT);

    cudaFuncSetAttribute(gemm1_proj, cudaFuncAttributeMaxDynamicSharedMemorySize, SMEMB);
    cudaFuncSetAttribute(gemm1<0>,   cudaFuncAttributeMaxDynamicSharedMemorySize, SMEMB);
    cudaFuncSetAttribute(gemm1<1>,   cudaFuncAttributeMaxDynamicSharedMemorySize, SMEMB);

    const size_t DDe = (size_t)Dv * Dv;
    const size_t PNe = (size_t)BNROWS * Dv;
    dim3 tb32(32, 8);

    // 1) conversions
    conv_x<<<(unsigned)(PNe/4/256), 256>>>(x, X);
    conv_wT<<<dim3(Dv/32, Dv/32, 4), tb32>>>(w[0], w[1], w[2], w[3], WT);

    // 2) all four projections in ONE launch (z=0: q gate; z=1: k/v transpose)
    gemm1_proj<<<dim3(Dv/64, BNROWS/128, 2), 256, SMEMB>>>(
        X, WT + 0*DDe, WT + 1*DDe, WT + 2*DDe, WT + 3*DDe,
        Q, KT, VT, Dv, Dv);

    // 3) kv[b] = k^T@v -> kv^T fp16 [Dv][Dv]
    gemm1<1><<<dim3(Dv/128, Dv/128, Bv), 512, SMEMB>>>(
        KT, VT, nullptr, KVT, Dv, Dv, Nv, (long)Dv*Nv, (long)Dv*Nv, (long)DDe);

    // 4) out[b] = q@kv -> fp32
    gemm1<0><<<dim3(Dv/128, Nv/128, Bv), 512, SMEMB>>>(
        Q, KVT, out, nullptr, Nv, Dv, Dv, (long)Nv*Dv, (long)DDe, (long)Nv*Dv);
}

// round 16
// speedup vs baseline: 1.1250x; 1.1250x over previous
#include <cuda_runtime.h>
#include <cuda_fp16.h>
#include <cstdint>

// LinearAttention B=4, N=4096, D=1024 fp32
// R16: R14 structure (2 CTAs/SM, 256 thr) + K-chunk 64 (128B rows, SW128,
//      NST=3): half the barriers, 2x MMAs per sync window.

#define Bv 4
#define Nv 4096
#define Dv 1024
#define BNROWS (Bv*Nv)            // 16384

#define NST 3
#define STG 32768                 // 32KB stage: A 16KB + B 16KB (or B1/B2 8KB)
#define SMEMB (NST*STG)           // 98304; x2 CTA/SM = 192KB <= 228KB

#define SWZ128(x) ((x) ^ (((x) >> 3) & 0x70))

// ------------------------------ scratch -----------------------------------
__device__ __align__(16) __half g_X  [(size_t)BNROWS*Dv];
__device__ __align__(16) __half g_WT [4][1024*1024];
__device__ __align__(16) __half g_Q  [(size_t)BNROWS*Dv];
__device__ __align__(16) __half g_KT [(size_t)Bv*Dv*Nv];
__device__ __align__(16) __half g_VT [(size_t)Bv*Dv*Nv];
__device__ __align__(16) __half g_KVT[(size_t)Bv*Dv*Dv];

// ------------------------------ helpers ------------------------------------
__device__ __forceinline__ uint32_t s2u(const void* p) {
    uint32_t a;
    asm("{ .reg .u64 t; cvta.to.shared.u64 t, %1; cvt.u32.u64 %0, t; }" : "=r"(a) : "l"(p));
    return a;
}
__device__ __forceinline__ void cpa16(uint32_t dst, const void* src) {
    asm volatile("cp.async.cg.shared.global [%0], [%1], 16;" :: "r"(dst), "l"(src));
}
#define CPC() asm volatile("cp.async.commit_group;" ::: "memory")
#define WAITG(n) asm volatile("cp.async.wait_group %0;" :: "n"(n) : "memory")

__device__ __forceinline__ void ldsm4(uint32_t* r, uint32_t addr) {
    asm volatile("ldmatrix.sync.aligned.m8n8.x4.shared.b16 {%0,%1,%2,%3}, [%4];"
                 : "=r"(r[0]), "=r"(r[1]), "=r"(r[2]), "=r"(r[3]) : "r"(addr));
}
__device__ __forceinline__ void mmaf16(float* c, const uint32_t* a, const uint32_t* b) {
    asm volatile(
        "mma.sync.aligned.m16n8k16.row.col.f32.f16.f16.f32 "
        "{%0,%1,%2,%3}, {%4,%5,%6,%7}, {%8,%9}, {%0,%1,%2,%3};"
        : "+f"(c[0]), "+f"(c[1]), "+f"(c[2]), "+f"(c[3])
        : "r"(a[0]), "r"(a[1]), "r"(a[2]), "r"(a[3]), "r"(b[0]), "r"(b[1]));
}
__device__ __forceinline__ uint32_t packh2(float f0, float f1) {
    return ((uint32_t)__half_as_ushort(__float2half_rn(f1)) << 16)
         | __half_as_ushort(__float2half_rn(f0));
}

// ldmatrix fragment address, 128B rows with SW128:
//   addr(ks) = (pre | ks*32) ^ m, pre = row*128 + colsel (bits 5..6 zero),
//   m = (row & 7) << 4  (swizzle mask depends only on row).
struct Frag { uint32_t pre, m; };
__device__ __forceinline__ Frag mkfrag(uint32_t row, uint32_t colsel) {
    Frag f; f.pre = row * 128 + colsel; f.m = (row & 7u) << 4; return f;
}
__device__ __forceinline__ uint32_t faddr(const Frag& f, int ks) {
    return (f.pre | ((uint32_t)ks << 5)) ^ f.m;
}

// --------------- merged projection GEMM (dual-B, CTA 128x64) ----------------
// 256 thr, 2 CTA/SM, warp 32x32, K-chunk 64.
// z=0: q=C1*C2 straight fp16. z=1: C1,C2 -> transposed fp16 into KT,VT.
__global__ __launch_bounds__(256, 2)
void gemm1_proj(const __half* __restrict__ Ag,
                const __half* __restrict__ W0, const __half* __restrict__ W1,
                const __half* __restrict__ W2, const __half* __restrict__ W3,
                __half* __restrict__ Q, __half* __restrict__ KT,
                __half* __restrict__ VT, int N, int Kg)
{
    extern __shared__ char sm[];
    const uint32_t smu = s2u(sm);
    const int tid = threadIdx.x, lane = tid & 31, wid = tid >> 5;
    const int bm = blockIdx.y * 128, bn = blockIdx.x * 64;
    const int wm = (wid & 3) * 32, wn = (wid >> 2) * 32;
    const int job = blockIdx.z;

    const __half* B1 = (job == 0) ? W0 : W2;
    const __half* B2 = (job == 0) ? W1 : W3;

    // loads: 128B rows, 8 x 16B groups; rA = tid>>3 (0..31), g = tid&7
    const int rA = tid >> 3, g = tid & 7;
    uint32_t soA[4], soB[2];
#pragma unroll
    for (int i = 0; i < 4; i++) soA[i] = SWZ128((uint32_t)((rA + i*32) * 128 + g * 16));
#pragma unroll
    for (int i = 0; i < 2; i++) soB[i] = soA[i];
    const __half* gA = Ag + (size_t)(bm + rA) * Kg + g * 8;
    const __half* g1 = B1 + (size_t)(bn + rA) * Kg + g * 8;
    const __half* g2 = B2 + (size_t)(bn + rA) * Kg + g * 8;
    const size_t rstep = (size_t)32 * Kg;

    Frag fa[2], fb[2];
    {
        uint32_t arow = (uint32_t)(wm + (lane & 15));
        uint32_t acol = (uint32_t)((lane >> 4) * 16);
        uint32_t brow = (uint32_t)(wn + ((lane >> 4) << 3) + (lane & 7));
        uint32_t bcol = (uint32_t)(((lane >> 3) & 1) * 16);
#pragma unroll
        for (int mi = 0; mi < 2; mi++) fa[mi] = mkfrag(arow + mi * 16, acol);
#pragma unroll
        for (int gg = 0; gg < 2; gg++)  fb[gg] = mkfrag(brow + gg * 16, bcol);
    }

    float a1[2][4][4], a2[2][4][4];
#pragma unroll
    for (int mi = 0; mi < 2; mi++)
#pragma unroll
        for (int ni = 0; ni < 4; ni++)
#pragma unroll
            for (int j = 0; j < 4; j++) { a1[mi][ni][j] = 0.0f; a2[mi][ni][j] = 0.0f; }

    const int nch = Kg / 64;
    auto load_stage = [&](int c) {
        const uint32_t st = smu + (uint32_t)(c % NST) * STG;
        const int k0 = c * 64;
#pragma unroll
        for (int i = 0; i < 4; i++)
            cpa16(st + soA[i], gA + k0 + i * rstep);            // A 128 rows
#pragma unroll
        for (int i = 0; i < 2; i++) {
            cpa16(st + 16384 + soB[i], g1 + k0 + i * rstep);    // B1 64 rows
            cpa16(st + 24576 + soB[i], g2 + k0 + i * rstep);    // B2 64 rows
        }
        CPC();
    };

    load_stage(0); load_stage(1);

    for (int c = 0; c < nch; ++c) {
        if (c + 1 < nch) WAITG(1); else WAITG(0);
        __syncthreads();
        if (c + 2 < nch) load_stage(c + 2);

        const uint32_t st = smu + (uint32_t)(c % NST) * STG;
#pragma unroll
        for (int ks = 0; ks < 4; ks++) {
            uint32_t ah[2][4], t1[2][4], t2[2][4];
#pragma unroll
            for (int mi = 0; mi < 2; mi++)
                ldsm4(ah[mi], st + faddr(fa[mi], ks));
#pragma unroll
            for (int gg = 0; gg < 2; gg++) {
                ldsm4(t1[gg], st + 16384 + faddr(fb[gg], ks));
                ldsm4(t2[gg], st + 24576 + faddr(fb[gg], ks));
            }
#pragma unroll
            for (int gg = 0; gg < 2; gg++)
#pragma unroll
                for (int mi = 0; mi < 2; mi++) {
                    mmaf16(a1[mi][2*gg],   ah[mi], t1[gg]);
                    mmaf16(a1[mi][2*gg+1], ah[mi], t1[gg] + 2);
                    mmaf16(a2[mi][2*gg],   ah[mi], t2[gg]);
                    mmaf16(a2[mi][2*gg+1], ah[mi], t2[gg] + 2);
                }
        }
    }

    if (job == 0) {
#pragma unroll
        for (int mi = 0; mi < 2; mi++) {
            int r = bm + wm + mi * 16 + (lane >> 2);
#pragma unroll
            for (int ni = 0; ni < 4; ni++) {
                int c = bn + wn + ni * 8 + (lane & 3) * 2;
                *(uint32_t*)(Q + (size_t)r * N + c) =
                    packh2(a1[mi][ni][0]*a2[mi][ni][0], a1[mi][ni][1]*a2[mi][ni][1]);
                *(uint32_t*)(Q + (size_t)(r + 8) * N + c) =
                    packh2(a1[mi][ni][2]*a2[mi][ni][2], a1[mi][ni][3]*a2[mi][ni][3]);
            }
        }
    } else {
        size_t batch = (size_t)(bm >> 12);
        size_t base = batch * (size_t)Dv * Nv + (size_t)bn * Nv + (bm & 4095);
        __half* s16 = (__half*)sm;
        const int LDS = 72;
        const float (*accs[2])[4][4] = { a1, a2 };
        __half* outs[2] = { KT, VT };
#pragma unroll
        for (int w = 0; w < 2; w++) {
            __syncthreads();
#pragma unroll
            for (int mi = 0; mi < 2; mi++) {
                int r = wm + mi * 16 + (lane >> 2);
#pragma unroll
                for (int ni = 0; ni < 4; ni++) {
                    int c = wn + ni * 8 + (lane & 3) * 2;
                    s16[r * LDS + c]           = __float2half_rn(accs[w][mi][ni][0]);
                    s16[r * LDS + c + 1]       = __float2half_rn(accs[w][mi][ni][1]);
                    s16[(r + 8) * LDS + c]     = __float2half_rn(accs[w][mi][ni][2]);
                    s16[(r + 8) * LDS + c + 1] = __float2half_rn(accs[w][mi][ni][3]);
                }
            }
            __syncthreads();
            int d = tid >> 2, nb = (tid & 3) * 32;
            __half* rh = outs[w] + base + (size_t)d * Nv + nb;
#pragma unroll
            for (int j = 0; j < 4; j++) {
                alignas(16) __half hb[8];
#pragma unroll
                for (int i = 0; i < 8; i++)
                    hb[i] = s16[(nb + j * 8 + i) * LDS + d];
                *(uint4*)(rh + j * 8) = *(const uint4*)hb;
            }
        }
    }
}

// --------------- single-B 1-pass GEMM (kv / out), CTA 128x128 ---------------
// 256 thr, 2 CTA/SM, warp 32x64, K-chunk 64. MODE 0: fp32. MODE 1: trans fp16.
template<int MODE>
__global__ __launch_bounds__(256, 2)
void gemm1(const __half* __restrict__ Ag, const __half* __restrict__ Bg,
           float* __restrict__ Cf, __half* __restrict__ OH,
           int M, int N, int Kg, long sA, long sB, long sO)
{
    extern __shared__ char sm[];
    const uint32_t smu = s2u(sm);
    const int tid = threadIdx.x, lane = tid & 31, wid = tid >> 5;
    const int bm = blockIdx.y * 128, bn = blockIdx.x * 128;
    const int wm = (wid & 3) * 32, wn = (wid >> 2) * 64;

    const __half* Ap = Ag + (size_t)blockIdx.z * sA;
    const __half* Bp = Bg + (size_t)blockIdx.z * sB;

    const int rA = tid >> 3, g = tid & 7;
    uint32_t so[4];
#pragma unroll
    for (int i = 0; i < 4; i++) so[i] = SWZ128((uint32_t)((rA + i*32) * 128 + g * 16));
    const __half* gA = Ap + (size_t)(bm + rA) * Kg + g * 8;
    const __half* gB = Bp + (size_t)(bn + rA) * Kg + g * 8;
    const size_t rstep = (size_t)32 * Kg;

    Frag fa[2], fb[4];
    {
        uint32_t arow = (uint32_t)(wm + (lane & 15));
        uint32_t acol = (uint32_t)((lane >> 4) * 16);
        uint32_t brow = (uint32_t)(wn + ((lane >> 4) << 3) + (lane & 7));
        uint32_t bcol = (uint32_t)(((lane >> 3) & 1) * 16);
#pragma unroll
        for (int mi = 0; mi < 2; mi++) fa[mi] = mkfrag(arow + mi * 16, acol);
#pragma unroll
        for (int gg = 0; gg < 4; gg++)  fb[gg] = mkfrag(brow + gg * 16, bcol);
    }

    float acc[2][8][4];
#pragma unroll
    for (int mi = 0; mi < 2; mi++)
#pragma unroll
        for (int ni = 0; ni < 8; ni++)
#pragma unroll
            for (int j = 0; j < 4; j++) acc[mi][ni][j] = 0.0f;

    const int nch = Kg / 64;
    auto load_stage = [&](int c) {
        const uint32_t st = smu + (uint32_t)(c % NST) * STG;
        const int k0 = c * 64;
#pragma unroll
        for (int i = 0; i < 4; i++) {
            cpa16(st + so[i],         gA + k0 + i * rstep);
            cpa16(st + 16384 + so[i], gB + k0 + i * rstep);
        }
        CPC();
    };

    load_stage(0); load_stage(1);

    for (int c = 0; c < nch; ++c) {
        if (c + 1 < nch) WAITG(1); else WAITG(0);
        __syncthreads();
        if (c + 2 < nch) load_stage(c + 2);

        const uint32_t st = smu + (uint32_t)(c % NST) * STG;
#pragma unroll
        for (int ks = 0; ks < 4; ks++) {
            uint32_t ah[2][4], tb[4][4];
#pragma unroll
            for (int mi = 0; mi < 2; mi++)
                ldsm4(ah[mi], st + faddr(fa[mi], ks));
#pragma unroll
            for (int gg = 0; gg < 4; gg++)
                ldsm4(tb[gg], st + 16384 + faddr(fb[gg], ks));
#pragma unroll
            for (int gg = 0; gg < 4; gg++)
#pragma unroll
                for (int mi = 0; mi < 2; mi++) {
                    mmaf16(acc[mi][2*gg],   ah[mi], tb[gg]);
                    mmaf16(acc[mi][2*gg+1], ah[mi], tb[gg] + 2);
                }
        }
    }

    if (MODE == 0) {
        float* Cb = Cf + (size_t)blockIdx.z * sO;
#pragma unroll
        for (int mi = 0; mi < 2; mi++) {
            int rr = bm + wm + mi * 16 + (lane >> 2);
#pragma unroll
            for (int ni = 0; ni < 8; ni++) {
                int col = bn + wn + ni * 8 + (lane & 3) * 2;
                *(float2*)(Cb + (size_t)rr * N + col)       = make_float2(acc[mi][ni][0], acc[mi][ni][1]);
                *(float2*)(Cb + (size_t)(rr + 8) * N + col) = make_float2(acc[mi][ni][2], acc[mi][ni][3]);
            }
        }
    } else {
        // transpose 128x128 tile -> fp16 rows (bn+d), cols bm.. (LDS=136 halfs)
        size_t base = (size_t)blockIdx.z * sO + (size_t)bn * M + bm;
        __half* s16 = (__half*)sm;
        const int LDS = 136;
        __syncthreads();
#pragma unroll
        for (int mi = 0; mi < 2; mi++) {
            int r = wm + mi * 16 + (lane >> 2);
#pragma unroll
            for (int ni = 0; ni < 8; ni++) {
                int c = wn + ni * 8 + (lane & 3) * 2;
                s16[r * LDS + c]           = __float2half_rn(acc[mi][ni][0]);
                s16[r * LDS + c + 1]       = __float2half_rn(acc[mi][ni][1]);
                s16[(r + 8) * LDS + c]     = __float2half_rn(acc[mi][ni][2]);
                s16[(r + 8) * LDS + c + 1] = __float2half_rn(acc[mi][ni][3]);
            }
        }
        __syncthreads();
        int d = tid >> 1, nb = (tid & 1) * 64;
        __half* rh = OH + base + (size_t)d * M + nb;
#pragma unroll
        for (int j = 0; j < 8; j++) {
            alignas(16) __half hb[8];
#pragma unroll
            for (int i = 0; i < 8; i++)
                hb[i] = s16[(nb + j * 8 + i) * LDS + d];
            *(uint4*)(rh + j * 8) = *(const uint4*)hb;
        }
    }
}

// --------------------------- conversion kernels ----------------------------
__global__ void conv_x(const float* __restrict__ in, __half* __restrict__ o) {
    size_t i = (size_t)blockIdx.x * blockDim.x + threadIdx.x;
    float4 f = ((const float4*)in)[i];
    ((__half2*)o)[i*2]   = __halves2half2(__float2half_rn(f.x), __float2half_rn(f.y));
    ((__half2*)o)[i*2+1] = __halves2half2(__float2half_rn(f.z), __float2half_rn(f.w));
}

__global__ void conv_wT(const float* w0, const float* w1, const float* w2, const float* w3,
                        __half* __restrict__ O) {
    const float* in = (blockIdx.z == 0) ? w0 : (blockIdx.z == 1) ? w1
                     : (blockIdx.z == 2) ? w2 : w3;
    __half* o = O + (size_t)blockIdx.z * Dv * Dv;
    __shared__ float t[32][33];
    int c0 = blockIdx.x * 32, r0 = blockIdx.y * 32;
    int tx = threadIdx.x, ty = threadIdx.y;
#pragma unroll
    for (int i = 0; i < 4; i++)
        t[ty + i*8][tx] = in[(size_t)(r0 + ty + i*8) * Dv + c0 + tx];
    __syncthreads();
#pragma unroll
    for (int i = 0; i < 4; i++) {
        int oc = c0 + ty + i*8, od = r0 + tx;
        o[(size_t)oc * Dv + od] = __float2half_rn(t[tx][ty + i*8]);
    }
}

// ------------------------------- launch ------------------------------------
extern "C" void kernel_launch(void* const* d_in, const int* in_sizes, int n_in,
                              void* d_out, int out_size) {
    const float* x   = (const float*)d_in[0];
    const float* w[4] = { (const float*)d_in[1], (const float*)d_in[2],
                          (const float*)d_in[3], (const float*)d_in[4] };
    float* out = (float*)d_out;

    __half *X,*WT,*Q,*KT,*VT,*KVT;
    cudaGetSymbolAddress((void**)&X,   g_X);
    cudaGetSymbolAddress((void**)&WT,  g_WT);
    cudaGetSymbolAddress((void**)&Q,   g_Q);
    cudaGetSymbolAddress((void**)&KT,  g_KT);  cudaGetSymbolAddress((void**)&VT,  g_VT);
    cudaGetSymbolAddress((void**)&KVT, g_KVT);

    cudaFuncSetAttribute(gemm1_proj, cudaFuncAttributeMaxDynamicSharedMemorySize, SMEMB);
    cudaFuncSetAttribute(gemm1<0>,   cudaFuncAttributeMaxDynamicSharedMemorySize, SMEMB);
    cudaFuncSetAttribute(gemm1<1>,   cudaFuncAttributeMaxDynamicSharedMemorySize, SMEMB);

    const size_t DDe = (size_t)Dv * Dv;
    const size_t PNe = (size_t)BNROWS * Dv;
    dim3 tb32(32, 8);

    // 1) conversions
    conv_x<<<(unsigned)(PNe/4/256), 256>>>(x, X);
    conv_wT<<<dim3(Dv/32, Dv/32, 4), tb32>>>(w[0], w[1], w[2], w[3], WT);

    // 2) all four projections in ONE launch (z=0: q gate; z=1: k/v transpose)
    gemm1_proj<<<dim3(Dv/64, BNROWS/128, 2), 256, SMEMB>>>(
        X, WT + 0*DDe, WT + 1*DDe, WT + 2*DDe, WT + 3*DDe,
        Q, KT, VT, Dv, Dv);

    // 3) kv[b] = k^T@v -> kv^T fp16 [Dv][Dv]
    gemm1<1><<<dim3(Dv/128, Dv/128, Bv), 256, SMEMB>>>(
        KT, VT, nullptr, KVT, Dv, Dv, Nv, (long)Dv*Nv, (long)Dv*Nv, (long)DDe);

    // 4) out[b] = q@kv -> fp32
    gemm1<0><<<dim3(Dv/128, Nv/128, Bv), 256, SMEMB>>>(
        Q, KVT, out, nullptr, Nv, Dv, Dv, (long)Nv*Dv, (long)DDe, (long)Nv*Dv);
}